// round 12
// baseline (speedup 1.0000x reference)
#include <cuda_runtime.h>
#include <math.h>

// Problem constants
#define BS    4
#define CC    64
#define HH    128
#define WW    128
#define HW    (HH * WW)
#define NPIX  (BS * HW)        // 65536 pixels
#define NTOT  (NPIX * CC)      // 4194304 field elements
#define O2    128
#define DT    0.1f
#define THRESH 0.01
#define NSTEPS 50

// Step-kernel geometry: one warp processes 8 consecutive pixels as a batch
#define BLOCKS   512
#define THREADS  512
#define WARPS    16
#define PIXB     8

// SMEM layouts
#define W1P 128               // w1 row pitch: [c][o], contiguous LDS.128 at 4*lane
#define W2P 64                // w2 row pitch: [r][2*lane] channel pairs, rows o-permuted
#define BP  12                // f/h staging pitch (48B, 16B-aligned rows for LDS.128)
#define BUFW (O2 * BP)        // 1536 floats per warp (f rows 0..63 alias h rows 0..127)
#define SMEM_FLOATS (CC * W1P + O2 * W2P + WARPS * BUFW)
#define SMEM_BYTES  (SMEM_FLOATS * 4 + WARPS * 8)

// Persistent device state
__device__ float    g_f0[NTOT];
__device__ float    g_f1[NTOT];
__device__ int      g_done;
__device__ int      g_parity;
__device__ int      g_steps;
__device__ double   g_sum;
__device__ unsigned g_count;

__global__ void reset_kernel() {
    g_done = 0; g_parity = 0; g_steps = 0; g_sum = 0.0; g_count = 0u;
}

// NCHW -> NHWC
__global__ void nchw_to_nhwc(const float* __restrict__ in) {
    __shared__ float tile[32][33];
    int b  = blockIdx.z;
    int p0 = blockIdx.x * 32;
    int c0 = blockIdx.y * 32;
    const float* src = in   + (size_t)b * CC * HW;
    float*       dst = g_f0 + (size_t)b * HW * CC;
    for (int i = threadIdx.y; i < 32; i += 8)
        tile[i][threadIdx.x] = src[(size_t)(c0 + i) * HW + p0 + threadIdx.x];
    __syncthreads();
    for (int i = threadIdx.y; i < 32; i += 8)
        dst[(size_t)(p0 + i) * CC + c0 + threadIdx.x] = tile[threadIdx.x][i];
}

// NHWC (current parity) -> NCHW into d_out
__global__ void nhwc_to_nchw(float* __restrict__ out) {
    __shared__ float tile[32][33];
    const float* srcbuf = g_parity ? g_f1 : g_f0;
    int b  = blockIdx.z;
    int p0 = blockIdx.x * 32;
    int c0 = blockIdx.y * 32;
    const float* src = srcbuf + (size_t)b * HW * CC;
    float*       dst = out    + (size_t)b * CC * HW;
    for (int i = threadIdx.y; i < 32; i += 8)
        tile[i][threadIdx.x] = src[(size_t)(p0 + i) * CC + c0 + threadIdx.x];
    __syncthreads();
    for (int i = threadIdx.y; i < 32; i += 8)
        dst[(size_t)(c0 + i) * HW + p0 + threadIdx.x] = tile[threadIdx.x][i];
}

__global__ void write_steps(float* out, int out_size) {
    for (int i = NTOT; i < out_size; i++) out[i] = (float)g_steps;
}

__device__ __forceinline__ float gelu_exact(float v) {
    return 0.5f * v * (1.0f + erff(v * 0.70710678118654752440f));
}

// ---- packed f32x2 helpers (sm_103a FFMA2) ----
__device__ __forceinline__ unsigned long long dup2(float v) {
    unsigned long long r;
    asm("mov.b64 %0, {%1, %1};" : "=l"(r) : "f"(v));
    return r;
}
__device__ __forceinline__ void ffma2(unsigned long long& acc,
                                      unsigned long long a, unsigned long long b) {
    asm("fma.rn.f32x2 %0, %1, %2, %0;" : "+l"(acc) : "l"(a), "l"(b));
}
__device__ __forceinline__ void unpack2(unsigned long long v, float& lo, float& hi) {
    asm("mov.b64 {%0, %1}, %2;" : "=f"(lo), "=f"(hi) : "l"(v));
}

// Fused step: 8-pixel-per-warp batch; pixel operands read as 16B broadcasts.
__global__ __launch_bounds__(THREADS, 1)
void step_kernel(const float* __restrict__ dw, const float* __restrict__ db,
                 const float* __restrict__ w1, const float* __restrict__ b1,
                 const float* __restrict__ w2, const float* __restrict__ b2,
                 const float* __restrict__ dcoeff)
{
    if (g_done) return;

    extern __shared__ float smem[];
    float*  sW1  = smem;                          // [64][128]
    float*  sW2  = sW1 + CC * W1P;                // [128][64], rows r=(o&3)*32+(o>>2)
    float*  sBuf = sW2 + O2 * W2P;                // [16 warps][1536]
    double* sRed = (double*)(sBuf + WARPS * BUFW);

    const float* src = g_parity ? g_f1 : g_f0;
    float*       dst = g_parity ? g_f0 : g_f1;

    int tid = threadIdx.x;

    // Stage W1: w1[o*64+c] -> sW1[c*128 + o]
    for (int i = tid; i < CC * O2; i += THREADS) {
        int o = i >> 6, c = i & 63;
        sW1[c * W1P + o] = w1[i];
    }
    // Stage W2: w2[c*128+o] -> permuted row r, channel-pair packed
    for (int i = tid; i < CC * O2; i += THREADS) {
        int c = i >> 7, o = i & 127;
        int r = ((o & 3) << 5) + (o >> 2);
        sW2[r * W2P + ((c & 31) << 1) + (c >> 5)] = w2[i];
    }
    __syncthreads();

    int lane = tid & 31, wid = tid >> 5;
    float* sFw = sBuf + wid * BUFW;   // per-warp staging (f rows alias h rows)

    // Per-lane constants: lane owns channels {lane, lane+32}
    float dwr0[9], dwr1[9];
    #pragma unroll
    for (int k = 0; k < 9; k++) {
        dwr0[k] = dw[lane * 9 + k];
        dwr1[k] = dw[(lane + 32) * 9 + k];
    }
    float  dbr0 = db[lane], dbr1 = db[lane + 32];
    float4 b1v  = ((const float4*)b1)[lane];       // o = 4*lane .. 4*lane+3
    float  b2r0 = b2[lane], b2r1 = b2[lane + 32];
    float  dc   = dcoeff[0];

    // ---- Phase A: load f + depthwise conv for 8 consecutive pixels (one row) ----
    int p0 = (blockIdx.x * WARPS + wid) * PIXB;
    int b  = p0 >> 14;
    int y  = (p0 >> 7) & 127;
    int x  = p0 & 127;                              // multiple of 8
    const float* base = src + (size_t)b * (HW * CC);

    float fc0[PIXB], fc1[PIXB], d0[PIXB], d1[PIXB];
    #pragma unroll
    for (int i = 0; i < PIXB; i++) { d0[i] = dbr0; d1[i] = dbr1; }

    #pragma unroll
    for (int r = 0; r < 3; r++) {
        int yy = y + r - 1;
        bool rowok = (unsigned)yy < HH;
        #pragma unroll
        for (int cc = 0; cc < 10; cc++) {
            int xx = x + cc - 1;
            float v0 = 0.0f, v1 = 0.0f;
            if (rowok && (unsigned)xx < WW) {
                int ni = (yy * WW + xx) << 6;
                v0 = base[ni + lane];
                v1 = base[ni + 32 + lane];
            }
            if (r == 1 && cc >= 1 && cc <= 8) { fc0[cc - 1] = v0; fc1[cc - 1] = v1; }
            int plo = cc - 2 < 0 ? 0 : cc - 2;
            int phi = cc > 7 ? 7 : cc;
            #pragma unroll
            for (int pi = plo; pi <= phi; pi++) {
                int k = r * 3 + (cc - pi);
                d0[pi] = fmaf(dwr0[k], v0, d0[pi]);
                d1[pi] = fmaf(dwr1[k], v1, d1[pi]);
            }
        }
    }

    // Stage f: row c holds 8 pixel values, written as two float4 (16B-aligned)
    *(float4*)(sFw + lane * BP)            = make_float4(fc0[0], fc0[1], fc0[2], fc0[3]);
    *(float4*)(sFw + lane * BP + 4)        = make_float4(fc0[4], fc0[5], fc0[6], fc0[7]);
    *(float4*)(sFw + (lane + 32) * BP)     = make_float4(fc1[0], fc1[1], fc1[2], fc1[3]);
    *(float4*)(sFw + (lane + 32) * BP + 4) = make_float4(fc1[4], fc1[5], fc1[6], fc1[7]);
    __syncwarp();

    // ---- Phase B: GEMM1 h = gelu(W1 @ f + b1), f32x2 over pixel pairs ----
    // acc1[j][pp]: (h[4*lane+j][2pp], h[4*lane+j][2pp+1])
    unsigned long long acc1[4][4];
    #pragma unroll
    for (int j = 0; j < 4; j++) {
        unsigned long long bb = dup2(j == 0 ? b1v.x : j == 1 ? b1v.y : j == 2 ? b1v.z : b1v.w);
        #pragma unroll
        for (int pp = 0; pp < 4; pp++) acc1[j][pp] = bb;
    }
    #pragma unroll 8
    for (int c = 0; c < CC; c++) {
        float4 w = *(const float4*)(sW1 + c * W1P + (lane << 2));
        unsigned long long a0 = dup2(w.x), a1 = dup2(w.y), a2 = dup2(w.z), a3 = dup2(w.w);
        // 16B broadcast loads: each yields two f32x2 pixel-pair operands
        ulonglong2 fA = *(const ulonglong2*)(sFw + c * BP);       // pixels 0-3
        ulonglong2 fB = *(const ulonglong2*)(sFw + c * BP + 4);   // pixels 4-7
        ffma2(acc1[0][0], a0, fA.x); ffma2(acc1[0][1], a0, fA.y);
        ffma2(acc1[0][2], a0, fB.x); ffma2(acc1[0][3], a0, fB.y);
        ffma2(acc1[1][0], a1, fA.x); ffma2(acc1[1][1], a1, fA.y);
        ffma2(acc1[1][2], a1, fB.x); ffma2(acc1[1][3], a1, fB.y);
        ffma2(acc1[2][0], a2, fA.x); ffma2(acc1[2][1], a2, fA.y);
        ffma2(acc1[2][2], a2, fB.x); ffma2(acc1[2][3], a2, fB.y);
        ffma2(acc1[3][0], a3, fA.x); ffma2(acc1[3][1], a3, fA.y);
        ffma2(acc1[3][2], a3, fB.x); ffma2(acc1[3][3], a3, fB.y);
    }
    __syncwarp();

    // gelu + stage h at permuted rows r = j*32 + lane (one row per lane)
    #pragma unroll
    for (int j = 0; j < 4; j++) {
        float hv[8];
        #pragma unroll
        for (int pp = 0; pp < 4; pp++) {
            float lo, hi; unpack2(acc1[j][pp], lo, hi);
            hv[2 * pp]     = gelu_exact(lo);
            hv[2 * pp + 1] = gelu_exact(hi);
        }
        float* hrow = sFw + (j * 32 + lane) * BP;
        *(float4*)(hrow)     = make_float4(hv[0], hv[1], hv[2], hv[3]);
        *(float4*)(hrow + 4) = make_float4(hv[4], hv[5], hv[6], hv[7]);
    }
    __syncwarp();

    // ---- Phase C: GEMM2 react = W2 @ h + b2, f32x2 over pixel pairs ----
    unsigned long long acc2[2][4];
    {
        unsigned long long bb0 = dup2(b2r0), bb1 = dup2(b2r1);
        #pragma unroll
        for (int pp = 0; pp < 4; pp++) { acc2[0][pp] = bb0; acc2[1][pp] = bb1; }
    }
    #pragma unroll 8
    for (int r = 0; r < O2; r++) {
        float2 wv = *(const float2*)(sW2 + r * W2P + (lane << 1));
        unsigned long long a0 = dup2(wv.x), a1 = dup2(wv.y);
        ulonglong2 hA = *(const ulonglong2*)(sFw + r * BP);       // pixels 0-3
        ulonglong2 hB = *(const ulonglong2*)(sFw + r * BP + 4);   // pixels 4-7
        ffma2(acc2[0][0], a0, hA.x); ffma2(acc2[0][1], a0, hA.y);
        ffma2(acc2[0][2], a0, hB.x); ffma2(acc2[0][3], a0, hB.y);
        ffma2(acc2[1][0], a1, hA.x); ffma2(acc2[1][1], a1, hA.y);
        ffma2(acc2[1][2], a1, hB.x); ffma2(acc2[1][3], a1, hB.y);
    }

    // ---- Phase D: Euler update + |delta| ----
    float asum = 0.0f;
    float* dbase = dst + (size_t)b * (HW * CC);
    #pragma unroll
    for (int pp = 0; pp < 4; pp++) {
        float r0lo, r0hi, r1lo, r1hi;
        unpack2(acc2[0][pp], r0lo, r0hi);
        unpack2(acc2[1][pp], r1lo, r1hi);
        #pragma unroll
        for (int hf = 0; hf < 2; hf++) {
            int   pi = 2 * pp + hf;
            float r0 = hf ? r0hi : r0lo;
            float r1 = hf ? r1hi : r1lo;
            float n0 = fc0[pi] + DT * fmaf(dc, d0[pi], r0);
            float n1 = fc1[pi] + DT * fmaf(dc, d1[pi], r1);
            int ci = ((y * WW) + x + pi) << 6;
            dbase[ci + lane]      = n0;
            dbase[ci + 32 + lane] = n1;
            asum += fabsf(n0 - fc0[pi]) + fabsf(n1 - fc1[pi]);
        }
    }

    // ---- Reduction + fused finalize in last block ----
    #pragma unroll
    for (int off = 16; off; off >>= 1)
        asum += __shfl_xor_sync(0xffffffffu, asum, off);
    if (lane == 0) sRed[wid] = (double)asum;
    __syncthreads();
    if (tid == 0) {
        double s = 0.0;
        #pragma unroll
        for (int i = 0; i < WARPS; i++) s += sRed[i];
        atomicAdd(&g_sum, s);
        __threadfence();
        unsigned t = atomicInc(&g_count, BLOCKS - 1);
        if (t == BLOCKS - 1) {            // last block of this step: finalize
            double change = *((volatile double*)&g_sum) * (1.0 / (double)NTOT);
            g_steps += 1;
            g_parity ^= 1;
            if (change < THRESH) g_done = 1;
            g_sum = 0.0;
        }
    }
}

extern "C" void kernel_launch(void* const* d_in, const int* in_sizes, int n_in,
                              void* d_out, int out_size) {
    const float* field  = (const float*)d_in[0];
    const float* dw     = (const float*)d_in[1];
    const float* db     = (const float*)d_in[2];
    const float* w1     = (const float*)d_in[3];
    const float* b1     = (const float*)d_in[4];
    const float* w2     = (const float*)d_in[5];
    const float* b2     = (const float*)d_in[6];
    const float* dcoeff = (const float*)d_in[7];

    cudaFuncSetAttribute(step_kernel,
                         cudaFuncAttributeMaxDynamicSharedMemorySize, SMEM_BYTES);

    reset_kernel<<<1, 1>>>();

    dim3 tb(32, 8), tg(HW / 32, CC / 32, BS);
    nchw_to_nhwc<<<tg, tb>>>(field);

    for (int s = 0; s < NSTEPS; s++)
        step_kernel<<<BLOCKS, THREADS, SMEM_BYTES>>>(dw, db, w1, b1, w2, b2, dcoeff);

    nhwc_to_nchw<<<tg, tb>>>((float*)d_out);
    write_steps<<<1, 1>>>((float*)d_out, out_size);
}

// round 14
// speedup vs baseline: 1.5535x; 1.5535x over previous
#include <cuda_runtime.h>
#include <math.h>

// Problem constants
#define BS    4
#define CC    64
#define HH    128
#define WW    128
#define HW    (HH * WW)
#define NPIX  (BS * HW)        // 65536 pixels
#define NTOT  (NPIX * CC)      // 4194304 field elements
#define O2    128
#define DT    0.1f
#define THRESH 0.01
#define NSTEPS 50

// Step-kernel geometry (R8 config): one warp processes 8 consecutive pixels
#define BLOCKS   1024
#define THREADS  256
#define WARPS    8
#define PIXB     8

// SMEM layouts
#define W1P 132               // w1 row pitch: [c][o], LDS.128 at 4*lane (16B-aligned)
#define W2P 66                // w2 row pitch: [r][2*lane] channel pairs, rows o-permuted
#define BP  8                 // f/h staging pitch: 32B rows, 16B-aligned -> LDS.128 bcast
#define BUFW (O2 * BP)        // 1024 floats per warp (f rows 0..63 alias h rows 0..127)
#define SMEM_FLOATS (CC * W1P + O2 * W2P + WARPS * BUFW)
#define SMEM_BYTES  (SMEM_FLOATS * 4 + WARPS * 8)

// Persistent device state
__device__ float    g_f0[NTOT];
__device__ float    g_f1[NTOT];
__device__ int      g_done;
__device__ int      g_parity;
__device__ int      g_steps;
__device__ double   g_sum;
__device__ unsigned g_count;

__global__ void reset_kernel() {
    g_done = 0; g_parity = 0; g_steps = 0; g_sum = 0.0; g_count = 0u;
}

// NCHW -> NHWC
__global__ void nchw_to_nhwc(const float* __restrict__ in) {
    __shared__ float tile[32][33];
    int b  = blockIdx.z;
    int p0 = blockIdx.x * 32;
    int c0 = blockIdx.y * 32;
    const float* src = in   + (size_t)b * CC * HW;
    float*       dst = g_f0 + (size_t)b * HW * CC;
    for (int i = threadIdx.y; i < 32; i += 8)
        tile[i][threadIdx.x] = src[(size_t)(c0 + i) * HW + p0 + threadIdx.x];
    __syncthreads();
    for (int i = threadIdx.y; i < 32; i += 8)
        dst[(size_t)(p0 + i) * CC + c0 + threadIdx.x] = tile[threadIdx.x][i];
}

// NHWC (current parity) -> NCHW into d_out
__global__ void nhwc_to_nchw(float* __restrict__ out) {
    __shared__ float tile[32][33];
    const float* srcbuf = g_parity ? g_f1 : g_f0;
    int b  = blockIdx.z;
    int p0 = blockIdx.x * 32;
    int c0 = blockIdx.y * 32;
    const float* src = srcbuf + (size_t)b * HW * CC;
    float*       dst = out    + (size_t)b * CC * HW;
    for (int i = threadIdx.y; i < 32; i += 8)
        tile[i][threadIdx.x] = src[(size_t)(p0 + i) * CC + c0 + threadIdx.x];
    __syncthreads();
    for (int i = threadIdx.y; i < 32; i += 8)
        dst[(size_t)(c0 + i) * HW + p0 + threadIdx.x] = tile[threadIdx.x][i];
}

__global__ void write_steps(float* out, int out_size) {
    for (int i = NTOT; i < out_size; i++) out[i] = (float)g_steps;
}

__device__ __forceinline__ float gelu_exact(float v) {
    return 0.5f * v * (1.0f + erff(v * 0.70710678118654752440f));
}

// ---- packed f32x2 helpers (sm_103a FFMA2) ----
__device__ __forceinline__ unsigned long long dup2(float v) {
    unsigned long long r;
    asm("mov.b64 %0, {%1, %1};" : "=l"(r) : "f"(v));
    return r;
}
__device__ __forceinline__ void ffma2(unsigned long long& acc,
                                      unsigned long long a, unsigned long long b) {
    asm("fma.rn.f32x2 %0, %1, %2, %0;" : "+l"(acc) : "l"(a), "l"(b));
}
__device__ __forceinline__ void unpack2(unsigned long long v, float& lo, float& hi) {
    asm("mov.b64 {%0, %1}, %2;" : "=f"(lo), "=f"(hi) : "l"(v));
}
// 16B shared broadcast load -> two f32x2 operands
__device__ __forceinline__ void lds128_2x64(unsigned long long& a, unsigned long long& b,
                                            const float* p) {
    unsigned saddr = (unsigned)__cvta_generic_to_shared(p);
    asm volatile("ld.shared.v2.u64 {%0, %1}, [%2];" : "=l"(a), "=l"(b) : "r"(saddr));
}

// Fused step: 8-pixel-per-warp batch; weights read from SMEM once per batch.
__global__ __launch_bounds__(THREADS, 2)
void step_kernel(const float* __restrict__ dw, const float* __restrict__ db,
                 const float* __restrict__ w1, const float* __restrict__ b1,
                 const float* __restrict__ w2, const float* __restrict__ b2,
                 const float* __restrict__ dcoeff)
{
    if (g_done) return;

    extern __shared__ float smem[];
    float*  sW1  = smem;                          // [64][132]
    float*  sW2  = sW1 + CC * W1P;                // [128][66], rows r=(o&3)*32+(o>>2)
    float*  sBuf = sW2 + O2 * W2P;                // [8 warps][1024]
    double* sRed = (double*)(sBuf + WARPS * BUFW);

    const float* src = g_parity ? g_f1 : g_f0;
    float*       dst = g_parity ? g_f0 : g_f1;

    int tid = threadIdx.x;

    // Stage W1: w1[o*64+c] -> sW1[c*132 + o]
    for (int i = tid; i < CC * O2; i += THREADS) {
        int o = i >> 6, c = i & 63;
        sW1[c * W1P + o] = w1[i];
    }
    // Stage W2: w2[c*128+o] -> permuted row r, channel-pair packed
    for (int i = tid; i < CC * O2; i += THREADS) {
        int c = i >> 7, o = i & 127;
        int r = ((o & 3) << 5) + (o >> 2);
        sW2[r * W2P + ((c & 31) << 1) + (c >> 5)] = w2[i];
    }
    __syncthreads();

    int lane = tid & 31, wid = tid >> 5;
    float* sFw = sBuf + wid * BUFW;   // per-warp staging (f rows alias h rows)

    // Per-lane constants: lane owns channels {lane, lane+32}
    float dwr0[9], dwr1[9];
    #pragma unroll
    for (int k = 0; k < 9; k++) {
        dwr0[k] = dw[lane * 9 + k];
        dwr1[k] = dw[(lane + 32) * 9 + k];
    }
    float  dbr0 = db[lane], dbr1 = db[lane + 32];
    float4 b1v  = ((const float4*)b1)[lane];       // o = 4*lane .. 4*lane+3
    float  b2r0 = b2[lane], b2r1 = b2[lane + 32];
    float  dc   = dcoeff[0];

    // ---- Phase A: load f + depthwise conv for 8 consecutive pixels (one row) ----
    int p0 = (blockIdx.x * WARPS + wid) * PIXB;
    int b  = p0 >> 14;
    int y  = (p0 >> 7) & 127;
    int x  = p0 & 127;                              // multiple of 8
    const float* base = src + (size_t)b * (HW * CC);

    float fc0[PIXB], fc1[PIXB], d0[PIXB], d1[PIXB];
    #pragma unroll
    for (int i = 0; i < PIXB; i++) { d0[i] = dbr0; d1[i] = dbr1; }

    #pragma unroll
    for (int r = 0; r < 3; r++) {
        int yy = y + r - 1;
        bool rowok = (unsigned)yy < HH;
        #pragma unroll
        for (int cc = 0; cc < 10; cc++) {
            int xx = x + cc - 1;
            float v0 = 0.0f, v1 = 0.0f;
            if (rowok && (unsigned)xx < WW) {
                int ni = (yy * WW + xx) << 6;
                v0 = base[ni + lane];
                v1 = base[ni + 32 + lane];
            }
            if (r == 1 && cc >= 1 && cc <= 8) { fc0[cc - 1] = v0; fc1[cc - 1] = v1; }
            int plo = cc - 2 < 0 ? 0 : cc - 2;
            int phi = cc > 7 ? 7 : cc;
            #pragma unroll
            for (int pi = plo; pi <= phi; pi++) {
                int k = r * 3 + (cc - pi);
                d0[pi] = fmaf(dwr0[k], v0, d0[pi]);
                d1[pi] = fmaf(dwr1[k], v1, d1[pi]);
            }
        }
    }

    // Stage f: row c holds 8 pixel values (32B, 16B-aligned)
    *(float4*)(sFw + lane * BP)            = make_float4(fc0[0], fc0[1], fc0[2], fc0[3]);
    *(float4*)(sFw + lane * BP + 4)        = make_float4(fc0[4], fc0[5], fc0[6], fc0[7]);
    *(float4*)(sFw + (lane + 32) * BP)     = make_float4(fc1[0], fc1[1], fc1[2], fc1[3]);
    *(float4*)(sFw + (lane + 32) * BP + 4) = make_float4(fc1[4], fc1[5], fc1[6], fc1[7]);
    __syncwarp();

    // ---- Phase B: GEMM1 h = gelu(W1 @ f + b1), f32x2 over pixel pairs ----
    // acc1[j][pp]: (h[4*lane+j][2pp], h[4*lane+j][2pp+1])
    unsigned long long acc1[4][4];
    #pragma unroll
    for (int j = 0; j < 4; j++) {
        unsigned long long bb = dup2(j == 0 ? b1v.x : j == 1 ? b1v.y : j == 2 ? b1v.z : b1v.w);
        #pragma unroll
        for (int pp = 0; pp < 4; pp++) acc1[j][pp] = bb;
    }
    #pragma unroll 8
    for (int c = 0; c < CC; c++) {
        float4 w = *(const float4*)(sW1 + c * W1P + (lane << 2));
        unsigned long long a0 = dup2(w.x), a1 = dup2(w.y), a2 = dup2(w.z), a3 = dup2(w.w);
        unsigned long long fA0, fA1, fB0, fB1;
        lds128_2x64(fA0, fA1, sFw + c * BP);        // pixels 0-3 (two f32x2)
        lds128_2x64(fB0, fB1, sFw + c * BP + 4);    // pixels 4-7
        ffma2(acc1[0][0], a0, fA0); ffma2(acc1[0][1], a0, fA1);
        ffma2(acc1[0][2], a0, fB0); ffma2(acc1[0][3], a0, fB1);
        ffma2(acc1[1][0], a1, fA0); ffma2(acc1[1][1], a1, fA1);
        ffma2(acc1[1][2], a1, fB0); ffma2(acc1[1][3], a1, fB1);
        ffma2(acc1[2][0], a2, fA0); ffma2(acc1[2][1], a2, fA1);
        ffma2(acc1[2][2], a2, fB0); ffma2(acc1[2][3], a2, fB1);
        ffma2(acc1[3][0], a3, fA0); ffma2(acc1[3][1], a3, fA1);
        ffma2(acc1[3][2], a3, fB0); ffma2(acc1[3][3], a3, fB1);
    }
    __syncwarp();

    // gelu + stage h at permuted rows r = j*32 + lane (one 32B row per lane)
    #pragma unroll
    for (int j = 0; j < 4; j++) {
        float hv[8];
        #pragma unroll
        for (int pp = 0; pp < 4; pp++) {
            float lo, hi; unpack2(acc1[j][pp], lo, hi);
            hv[2 * pp]     = gelu_exact(lo);
            hv[2 * pp + 1] = gelu_exact(hi);
        }
        float* hrow = sFw + (j * 32 + lane) * BP;
        *(float4*)(hrow)     = make_float4(hv[0], hv[1], hv[2], hv[3]);
        *(float4*)(hrow + 4) = make_float4(hv[4], hv[5], hv[6], hv[7]);
    }
    __syncwarp();

    // ---- Phase C: GEMM2 react = W2 @ h + b2, f32x2 over pixel pairs ----
    unsigned long long acc2[2][4];
    {
        unsigned long long bb0 = dup2(b2r0), bb1 = dup2(b2r1);
        #pragma unroll
        for (int pp = 0; pp < 4; pp++) { acc2[0][pp] = bb0; acc2[1][pp] = bb1; }
    }
    #pragma unroll 8
    for (int r = 0; r < O2; r++) {
        float2 wv = *(const float2*)(sW2 + r * W2P + (lane << 1));
        unsigned long long a0 = dup2(wv.x), a1 = dup2(wv.y);
        unsigned long long hA0, hA1, hB0, hB1;
        lds128_2x64(hA0, hA1, sFw + r * BP);        // pixels 0-3
        lds128_2x64(hB0, hB1, sFw + r * BP + 4);    // pixels 4-7
        ffma2(acc2[0][0], a0, hA0); ffma2(acc2[0][1], a0, hA1);
        ffma2(acc2[0][2], a0, hB0); ffma2(acc2[0][3], a0, hB1);
        ffma2(acc2[1][0], a1, hA0); ffma2(acc2[1][1], a1, hA1);
        ffma2(acc2[1][2], a1, hB0); ffma2(acc2[1][3], a1, hB1);
    }

    // ---- Phase D: Euler update + |delta| ----
    float asum = 0.0f;
    float* dbase = dst + (size_t)b * (HW * CC);
    #pragma unroll
    for (int pp = 0; pp < 4; pp++) {
        float r0lo, r0hi, r1lo, r1hi;
        unpack2(acc2[0][pp], r0lo, r0hi);
        unpack2(acc2[1][pp], r1lo, r1hi);
        #pragma unroll
        for (int hf = 0; hf < 2; hf++) {
            int   pi = 2 * pp + hf;
            float r0 = hf ? r0hi : r0lo;
            float r1 = hf ? r1hi : r1lo;
            float n0 = fc0[pi] + DT * fmaf(dc, d0[pi], r0);
            float n1 = fc1[pi] + DT * fmaf(dc, d1[pi], r1);
            int ci = ((y * WW) + x + pi) << 6;
            dbase[ci + lane]      = n0;
            dbase[ci + 32 + lane] = n1;
            asum += fabsf(n0 - fc0[pi]) + fabsf(n1 - fc1[pi]);
        }
    }

    // ---- Reduction + fused finalize in last block ----
    #pragma unroll
    for (int off = 16; off; off >>= 1)
        asum += __shfl_xor_sync(0xffffffffu, asum, off);
    if (lane == 0) sRed[wid] = (double)asum;
    __syncthreads();
    if (tid == 0) {
        double s = 0.0;
        #pragma unroll
        for (int i = 0; i < WARPS; i++) s += sRed[i];
        atomicAdd(&g_sum, s);
        __threadfence();
        unsigned t = atomicInc(&g_count, BLOCKS - 1);
        if (t == BLOCKS - 1) {            // last block of this step: finalize
            double change = *((volatile double*)&g_sum) * (1.0 / (double)NTOT);
            g_steps += 1;
            g_parity ^= 1;
            if (change < THRESH) g_done = 1;
            g_sum = 0.0;
        }
    }
}

extern "C" void kernel_launch(void* const* d_in, const int* in_sizes, int n_in,
                              void* d_out, int out_size) {
    const float* field  = (const float*)d_in[0];
    const float* dw     = (const float*)d_in[1];
    const float* db     = (const float*)d_in[2];
    const float* w1     = (const float*)d_in[3];
    const float* b1     = (const float*)d_in[4];
    const float* w2     = (const float*)d_in[5];
    const float* b2     = (const float*)d_in[6];
    const float* dcoeff = (const float*)d_in[7];

    cudaFuncSetAttribute(step_kernel,
                         cudaFuncAttributeMaxDynamicSharedMemorySize, SMEM_BYTES);

    reset_kernel<<<1, 1>>>();

    dim3 tb(32, 8), tg(HW / 32, CC / 32, BS);
    nchw_to_nhwc<<<tg, tb>>>(field);

    for (int s = 0; s < NSTEPS; s++)
        step_kernel<<<BLOCKS, THREADS, SMEM_BYTES>>>(dw, db, w1, b1, w2, b2, dcoeff);

    nhwc_to_nchw<<<tg, tb>>>((float*)d_out);
    write_steps<<<1, 1>>>((float*)d_out, out_size);
}